// round 1
// baseline (speedup 1.0000x reference)
#include <cuda_runtime.h>
#include <cstdint>

// ---------------------------------------------------------------------------
// CharCountCNN: argmax-gather + concat -> conv1d(400->128,k3)+GN+ReLU
//               -> conv1d(128->64,k3)+GN+ReLU -> conv1d(64->32,k3)+GN+ReLU
//               -> conv1d(32->1,k1) -> *std + mean
//
// Decomposition: the 256 g_style channels are t-invariant and the 64
// char_style channels are a row gather from an 80-row table, so conv1 only
// loops over the 80 "real" input channels; the rest fold into precomputed
// gdot[b,o,k] and sdot[b,ch,o,k] tables added in the epilogue.
// GN apply+ReLU is fused into the NEXT conv's shared-memory load.
// ---------------------------------------------------------------------------

constexpr int T_   = 1024;
constexpr int NB   = 128;
constexpr int NCLS = 80;
constexpr int NSTY = 256;
constexpr int NCS  = 64;
constexpr int C1   = 128;
constexpr int C2   = 64;
constexpr int C3   = 32;
constexpr int CIN1W = 400;   // conv1 weight channel stride

// ------------------------- scratch (__device__ globals) --------------------
__device__ float d_xin [NB * NCLS * T_];        // transposed input  [b][c][t]
__device__ int   d_amax[NB * T_];               // argmax            [b][t]
__device__ float d_gdot[NB * C1 * 3];           // [b][o][k]
__device__ float d_sdot[NB * NCLS * C1 * 3];    // [b][ch][o][k]
__device__ float d_y1  [NB * C1 * T_];          // conv1 raw out [b][o][t]
__device__ float d_y2  [NB * C2 * T_];
__device__ float d_y3  [NB * C3 * T_];
__device__ float d_mean1[NB * 32], d_rstd1[NB * 32];
__device__ float d_mean2[NB * 32], d_rstd2[NB * 32];
__device__ float d_mean3[NB * 32], d_rstd3[NB * 32];

// ------------------------- K0: argmax + transpose --------------------------
// grid (T/128, NB), block 128. Each thread owns one t: reads its 80-float row
// (full 32B sectors per thread), tracks first-max argmax, stages into smem,
// then the block writes the 80xT transpose coalesced along t.
__global__ void __launch_bounds__(128) k_prep(const float* __restrict__ inp) {
    __shared__ float s[128][NCLS + 1];   // +1 pad -> stride 81 (conflict-free)
    const int b   = blockIdx.y;
    const int t0  = blockIdx.x * 128;
    const int tid = threadIdx.x;

    const float4* row = reinterpret_cast<const float4*>(
        inp + ((size_t)(t0 + tid) * NB + b) * NCLS);

    float best = -3.4e38f;
    int   bi   = 0;
#pragma unroll
    for (int c4 = 0; c4 < NCLS / 4; c4++) {
        float4 v = row[c4];
        int c = c4 * 4;
        s[tid][c + 0] = v.x; s[tid][c + 1] = v.y;
        s[tid][c + 2] = v.z; s[tid][c + 3] = v.w;
        if (v.x > best) { best = v.x; bi = c + 0; }
        if (v.y > best) { best = v.y; bi = c + 1; }
        if (v.z > best) { best = v.z; bi = c + 2; }
        if (v.w > best) { best = v.w; bi = c + 3; }
    }
    d_amax[b * T_ + t0 + tid] = bi;
    __syncthreads();
#pragma unroll 4
    for (int c = 0; c < NCLS; c++)
        d_xin[(b * NCLS + c) * T_ + t0 + tid] = s[tid][c];
}

// ------------------------- K1: gdot = w1_g . g_style -----------------------
// grid NB, block 384 (= 128 o * 3 k)
__global__ void __launch_bounds__(384) k_gdot(const float* __restrict__ g_style,
                                              const float* __restrict__ w1) {
    __shared__ float gs[NSTY];
    const int b = blockIdx.x, tid = threadIdx.x;
    for (int c = tid; c < NSTY; c += 384) gs[c] = g_style[b * NSTY + c];
    __syncthreads();
    const int o = tid / 3, k = tid % 3;
    const float* wp = w1 + o * (CIN1W * 3) + NCLS * 3 + k;
    float acc = 0.f;
#pragma unroll 8
    for (int c = 0; c < NSTY; c++) acc = fmaf(gs[c], wp[c * 3], acc);
    d_gdot[b * C1 * 3 + tid] = acc;
}

// ------------------------- K2: sdot = w1_s . char_style --------------------
// grid (NCLS, NB), block 384
__global__ void __launch_bounds__(384) k_sdot(const float* __restrict__ char_style,
                                              const float* __restrict__ w1) {
    __shared__ float cs[NCS];
    const int ch = blockIdx.x, b = blockIdx.y, tid = threadIdx.x;
    for (int c = tid; c < NCS; c += 384)
        cs[c] = char_style[((size_t)b * NCLS + ch) * NCS + c];
    __syncthreads();
    const int o = tid / 3, k = tid % 3;
    const float* wp = w1 + o * (CIN1W * 3) + (NCLS + NSTY) * 3 + k;
    float acc = 0.f;
#pragma unroll 8
    for (int c = 0; c < NCS; c++) acc = fmaf(cs[c], wp[c * 3], acc);
    d_sdot[((size_t)b * NCLS + ch) * C1 * 3 + tid] = acc;
}

// ------------------------- conv stage template -----------------------------
// STAGE 1: xin=d_xin (raw, 80ch), out=d_y1 (128ch), epilogue adds bias+gdot+sdot
// STAGE 2: xin=d_y1 with GN1+ReLU on load, out=d_y2
// STAGE 3: xin=d_y2 with GN2+ReLU on load, out=d_y3
// Block: 128 threads, tile BT=128 t x BO (64 or 32) o. Each thread: 8t x OT o.
template <int STAGE>
__global__ void __launch_bounds__(128)
k_conv(const float* __restrict__ w, const float* __restrict__ bias,
       const float* __restrict__ gns, const float* __restrict__ gnb) {
    constexpr int  CIN  = (STAGE == 1) ? NCLS : (STAGE == 2) ? C1 : C2;
    constexpr int  COUT = (STAGE == 1) ? C1   : (STAGE == 2) ? C2 : C3;
    constexpr int  CINW = (STAGE == 1) ? CIN1W : CIN;
    constexpr bool IS1  = (STAGE == 1);
    constexpr int  BT = 128;
    constexpr int  BO = (COUT >= 64) ? 64 : COUT;
    constexpr int  OT = BO / 8;
    constexpr int  CC = 8;

    const float* xin = IS1 ? d_xin : (STAGE == 2 ? d_y1 : d_y2);
    float*       y   = IS1 ? d_y1  : (STAGE == 2 ? d_y2 : d_y3);
    const float* mean = (STAGE == 2) ? d_mean1 : d_mean2;
    const float* rstd = (STAGE == 2) ? d_rstd1 : d_rstd2;

    const int b  = blockIdx.z;
    const int t0 = blockIdx.x * BT;
    const int o0 = blockIdx.y * BO;
    const int tid = threadIdx.x;
    const int tx = tid & 15;    // t group (8 t's each)
    const int ty = tid >> 4;    // o group (OT o's each)

    __shared__ float xs[CC][BT + 8];   // xs[cc][p] = x[t0-1+p], 16B-aligned rows
    __shared__ float ws[CC][BO * 3];
    __shared__ float sb[BO];
    __shared__ float gA[CIN], gB[CIN];
    __shared__ float sg[BO * 3];
    __shared__ int   sam[BT + 2];

    if constexpr (!IS1) {
        constexpr int CPG = CIN / 32;   // prev-layer channels per group
        for (int c = tid; c < CIN; c += 128) {
            const int g = c / CPG;
            const float a = rstd[b * 32 + g] * gns[c];
            gA[c] = a;
            gB[c] = gnb[c] - mean[b * 32 + g] * a;
        }
    }
    for (int o = tid; o < BO; o += 128) sb[o] = bias[o0 + o];
    if constexpr (IS1) {
        for (int i = tid; i < BO * 3; i += 128)
            sg[i] = d_gdot[b * C1 * 3 + o0 * 3 + i];
        for (int p = tid; p < BT + 2; p += 128) {
            const int t = t0 - 1 + p;
            sam[p] = (t >= 0 && t < T_) ? d_amax[b * T_ + t] : 0;
        }
    }
    __syncthreads();

    float acc[OT][8];
#pragma unroll
    for (int j = 0; j < OT; j++)
#pragma unroll
        for (int i = 0; i < 8; i++) acc[j][i] = 0.f;

    for (int c0 = 0; c0 < CIN; c0 += CC) {
        // stage x tile (with halo, zero-padded, GN+ReLU fused on load)
        for (int i = tid; i < CC * (BT + 2); i += 128) {
            const int cc = i / (BT + 2), p = i - cc * (BT + 2);
            const int t = t0 - 1 + p;
            const int c = c0 + cc;
            float v = 0.f;
            if (t >= 0 && t < T_) {
                v = xin[(b * CIN + c) * T_ + t];
                if constexpr (!IS1) v = fmaxf(fmaf(v, gA[c], gB[c]), 0.f);
            }
            xs[cc][p] = v;
        }
        // stage weights
        for (int i = tid; i < CC * BO * 3; i += 128) {
            const int cc = i / (BO * 3), r = i - cc * (BO * 3);
            ws[cc][r] = w[(o0 + r / 3) * (CINW * 3) + (c0 + cc) * 3 + (r % 3)];
        }
        __syncthreads();

#pragma unroll
        for (int cc = 0; cc < CC; cc++) {
            const float4* xp = reinterpret_cast<const float4*>(&xs[cc][tx * 8]);
            const float4 a0 = xp[0], a1 = xp[1], a2 = xp[2];
            const float xr[12] = {a0.x, a0.y, a0.z, a0.w,
                                  a1.x, a1.y, a1.z, a1.w,
                                  a2.x, a2.y, a2.z, a2.w};
#pragma unroll
            for (int j = 0; j < OT; j++) {
                const int ol = ty * OT + j;
                const float w0 = ws[cc][ol * 3 + 0];
                const float w1v = ws[cc][ol * 3 + 1];
                const float w2 = ws[cc][ol * 3 + 2];
#pragma unroll
                for (int i = 0; i < 8; i++)
                    acc[j][i] = fmaf(w0, xr[i],
                                fmaf(w1v, xr[i + 1],
                                fmaf(w2, xr[i + 2], acc[j][i])));
            }
        }
        __syncthreads();
    }

    // epilogue
#pragma unroll
    for (int j = 0; j < OT; j++) {
        const int ol = ty * OT + j;
#pragma unroll
        for (int i = 0; i < 8; i++) {
            const int tl = tx * 8 + i;
            const int t = t0 + tl;
            float v = acc[j][i] + sb[ol];
            if constexpr (IS1) {
                const int og = o0 + ol;
                const float* sd = d_sdot + (size_t)b * NCLS * C1 * 3;
                v += sg[ol * 3 + 1] + sd[(sam[tl + 1] * C1 + og) * 3 + 1];
                if (t > 0)
                    v += sg[ol * 3 + 0] + sd[(sam[tl] * C1 + og) * 3 + 0];
                if (t < T_ - 1)
                    v += sg[ol * 3 + 2] + sd[(sam[tl + 2] * C1 + og) * 3 + 2];
            }
            y[(b * COUT + o0 + ol) * T_ + t] = v;
        }
    }
}

// ------------------------- GN stats (mean / rstd per (b,group)) ------------
template <int STAGE>
__global__ void __launch_bounds__(128) k_gnstats() {
    constexpr int C   = (STAGE == 1) ? C1 : (STAGE == 2) ? C2 : C3;
    constexpr int CPG = C / 32;
    constexpr int N   = CPG * T_;
    const float* y   = (STAGE == 1) ? d_y1 : (STAGE == 2) ? d_y2 : d_y3;
    float* meanp = (STAGE == 1) ? d_mean1 : (STAGE == 2) ? d_mean2 : d_mean3;
    float* rstdp = (STAGE == 1) ? d_rstd1 : (STAGE == 2) ? d_rstd2 : d_rstd3;

    const int bg = blockIdx.x;
    const float* p = y + (size_t)(bg / 32) * C * T_ + (size_t)(bg % 32) * CPG * T_;
    float s = 0.f, s2 = 0.f;
    for (int i = threadIdx.x; i < N; i += 128) {
        const float v = p[i];
        s += v;
        s2 = fmaf(v, v, s2);
    }
    __shared__ float ss[4], ss2[4];
#pragma unroll
    for (int o = 16; o; o >>= 1) {
        s  += __shfl_down_sync(0xffffffffu, s,  o);
        s2 += __shfl_down_sync(0xffffffffu, s2, o);
    }
    if ((threadIdx.x & 31) == 0) { ss[threadIdx.x >> 5] = s; ss2[threadIdx.x >> 5] = s2; }
    __syncthreads();
    if (threadIdx.x == 0) {
        const float S  = ss[0] + ss[1] + ss[2] + ss[3];
        const float S2 = ss2[0] + ss2[1] + ss2[2] + ss2[3];
        const float m = S / N;
        const float var = S2 / N - m * m;
        meanp[bg] = m;
        rstdp[bg] = rsqrtf(var + 1e-5f);
    }
}

// ------------------------- conv4 (k=1) + output affine ---------------------
// grid (T/256, NB), block 256. GN3+ReLU fused on read of y3.
__global__ void __launch_bounds__(256)
k_out(const float* __restrict__ w4, const float* __restrict__ b4,
      const float* __restrict__ s3, const float* __restrict__ bb3,
      const float* __restrict__ omean, const float* __restrict__ ostd,
      float* __restrict__ out) {
    const int b = blockIdx.y;
    const int t = blockIdx.x * 256 + threadIdx.x;
    __shared__ float A[32], Bc[32], W[32];
    if (threadIdx.x < 32) {
        const int c = threadIdx.x;               // C3=32 -> 1 channel / group
        const float a = d_rstd3[b * 32 + c] * s3[c];
        A[c] = a;
        Bc[c] = bb3[c] - d_mean3[b * 32 + c] * a;
        W[c] = w4[c];
    }
    __syncthreads();
    float acc = b4[0];
#pragma unroll
    for (int c = 0; c < 32; c++) {
        float v = d_y3[(b * 32 + c) * T_ + t];
        v = fmaxf(fmaf(v, A[c], Bc[c]), 0.f);
        acc = fmaf(W[c], v, acc);
    }
    out[(size_t)t * NB + b] = fmaf(acc, ostd[0], omean[0]);
}

// ------------------------- launch ------------------------------------------
extern "C" void kernel_launch(void* const* d_in, const int* in_sizes, int n_in,
                              void* d_out, int out_size) {
    const float* input      = (const float*)d_in[0];
    const float* g_style    = (const float*)d_in[1];
    // d_in[2] = spacing_style (unused by reference)
    const float* char_style = (const float*)d_in[3];
    const float* c1w = (const float*)d_in[4];
    const float* c1b = (const float*)d_in[5];
    const float* g1s = (const float*)d_in[6];
    const float* g1b = (const float*)d_in[7];
    const float* c2w = (const float*)d_in[8];
    const float* c2b = (const float*)d_in[9];
    const float* g2s = (const float*)d_in[10];
    const float* g2b = (const float*)d_in[11];
    const float* c3w = (const float*)d_in[12];
    const float* c3b = (const float*)d_in[13];
    const float* g3s = (const float*)d_in[14];
    const float* g3b = (const float*)d_in[15];
    const float* c4w = (const float*)d_in[16];
    const float* c4b = (const float*)d_in[17];
    const float* om  = (const float*)d_in[18];
    const float* os  = (const float*)d_in[19];
    float* out = (float*)d_out;

    k_prep<<<dim3(T_ / 128, NB), 128>>>(input);
    k_gdot<<<NB, 384>>>(g_style, c1w);
    k_sdot<<<dim3(NCLS, NB), 384>>>(char_style, c1w);

    k_conv<1><<<dim3(T_ / 128, C1 / 64, NB), 128>>>(c1w, c1b, nullptr, nullptr);
    k_gnstats<1><<<NB * 32, 128>>>();

    k_conv<2><<<dim3(T_ / 128, 1, NB), 128>>>(c2w, c2b, g1s, g1b);
    k_gnstats<2><<<NB * 32, 128>>>();

    k_conv<3><<<dim3(T_ / 128, 1, NB), 128>>>(c3w, c3b, g2s, g2b);
    k_gnstats<3><<<NB * 32, 128>>>();

    k_out<<<dim3(T_ / 256, NB), 256>>>(c4w, c4b, g3s, g3b, om, os, out);
}

// round 5
// speedup vs baseline: 1.0007x; 1.0007x over previous
#include <cuda_runtime.h>
#include <cstdint>

// ---------------------------------------------------------------------------
// CharCountCNN — round 4: packed f32x2 FMA convs, double-buffered smem, CC=8
// (fits the 48KB static smem cap that killed round 3).
// ---------------------------------------------------------------------------

constexpr int T_   = 1024;
constexpr int NB   = 128;
constexpr int NCLS = 80;
constexpr int NSTY = 256;
constexpr int NCS  = 64;
constexpr int C1   = 128;
constexpr int C2   = 64;
constexpr int C3   = 32;
constexpr int CIN1W = 400;

// ------------------------- scratch -----------------------------------------
__device__ float d_xin [NB * NCLS * T_];
__device__ int   d_amax[NB * T_];
__device__ float d_gdot[NB * 3 * C1];           // [b][k][o]
__device__ float d_sdot[NB * NCLS * 3 * C1];    // [b][ch][k][o]
__device__ float d_y1  [NB * C1 * T_];
__device__ float d_y2  [NB * C2 * T_];
__device__ float d_y3  [NB * C3 * T_];
__device__ float d_mean1[NB * 32], d_rstd1[NB * 32];
__device__ float d_mean2[NB * 32], d_rstd2[NB * 32];
__device__ float d_mean3[NB * 32], d_rstd3[NB * 32];

// ------------------------- f32x2 helpers -----------------------------------
using u64 = unsigned long long;
__device__ __forceinline__ u64 pk2(float lo, float hi) {
    u64 r;
    asm("mov.b64 %0, {%1, %2};" : "=l"(r) : "f"(lo), "f"(hi));
    return r;
}
__device__ __forceinline__ void upk2(float& lo, float& hi, u64 v) {
    asm("mov.b64 {%0, %1}, %2;" : "=f"(lo), "=f"(hi) : "l"(v));
}
__device__ __forceinline__ void ffma2(u64& d, u64 a, u64 b) {
    asm("fma.rn.f32x2 %0, %1, %2, %0;" : "+l"(d) : "l"(a), "l"(b));
}

// ------------------------- K0: argmax + transpose --------------------------
__global__ void __launch_bounds__(128) k_prep(const float* __restrict__ inp) {
    __shared__ float s[128][NCLS + 1];
    const int b   = blockIdx.y;
    const int t0  = blockIdx.x * 128;
    const int tid = threadIdx.x;

    const float4* row = reinterpret_cast<const float4*>(
        inp + ((size_t)(t0 + tid) * NB + b) * NCLS);

    float best = -3.4e38f;
    int   bi   = 0;
#pragma unroll
    for (int c4 = 0; c4 < NCLS / 4; c4++) {
        float4 v = row[c4];
        int c = c4 * 4;
        s[tid][c + 0] = v.x; s[tid][c + 1] = v.y;
        s[tid][c + 2] = v.z; s[tid][c + 3] = v.w;
        if (v.x > best) { best = v.x; bi = c + 0; }
        if (v.y > best) { best = v.y; bi = c + 1; }
        if (v.z > best) { best = v.z; bi = c + 2; }
        if (v.w > best) { best = v.w; bi = c + 3; }
    }
    d_amax[b * T_ + t0 + tid] = bi;
    __syncthreads();
#pragma unroll 4
    for (int c = 0; c < NCLS; c++)
        d_xin[(b * NCLS + c) * T_ + t0 + tid] = s[tid][c];
}

// ------------------------- K1: gdot ----------------------------------------
__global__ void __launch_bounds__(384) k_gdot(const float* __restrict__ g_style,
                                              const float* __restrict__ w1) {
    __shared__ float gs[NSTY];
    const int b = blockIdx.x, tid = threadIdx.x;
    for (int c = tid; c < NSTY; c += 384) gs[c] = g_style[b * NSTY + c];
    __syncthreads();
    const int o = tid / 3, k = tid % 3;
    const float* wp = w1 + o * (CIN1W * 3) + NCLS * 3 + k;
    float acc = 0.f;
#pragma unroll 8
    for (int c = 0; c < NSTY; c++) acc = fmaf(gs[c], wp[c * 3], acc);
    d_gdot[b * 3 * C1 + k * C1 + o] = acc;
}

// ------------------------- K2: sdot ----------------------------------------
__global__ void __launch_bounds__(384) k_sdot(const float* __restrict__ char_style,
                                              const float* __restrict__ w1) {
    __shared__ float cs[NCS];
    const int ch = blockIdx.x, b = blockIdx.y, tid = threadIdx.x;
    for (int c = tid; c < NCS; c += 384)
        cs[c] = char_style[((size_t)b * NCLS + ch) * NCS + c];
    __syncthreads();
    const int o = tid / 3, k = tid % 3;
    const float* wp = w1 + o * (CIN1W * 3) + (NCLS + NSTY) * 3 + k;
    float acc = 0.f;
#pragma unroll 8
    for (int c = 0; c < NCS; c++) acc = fmaf(cs[c], wp[c * 3], acc);
    d_sdot[((size_t)b * NCLS + ch) * 3 * C1 + k * C1 + o] = acc;
}

// ------------------------- conv stage (packed f32x2, double-buffered) ------
// Block 256, tile BT=128 t x BO o. Thread: 8t x OT o. CC=8 channel chunks.
template <int STAGE>
__global__ void __launch_bounds__(256)
k_conv(const float* __restrict__ w, const float* __restrict__ bias,
       const float* __restrict__ gns, const float* __restrict__ gnb) {
    constexpr int  CIN  = (STAGE == 1) ? NCLS : (STAGE == 2) ? C1 : C2;
    constexpr int  COUT = (STAGE == 1) ? C1   : (STAGE == 2) ? C2 : C3;
    constexpr int  CINW = (STAGE == 1) ? CIN1W : CIN;
    constexpr bool IS1  = (STAGE == 1);
    constexpr int  BT = 128;
    constexpr int  BO = (COUT >= 64) ? 64 : COUT;
    constexpr int  OT = BO / 16;         // 4 / 4 / 2
    constexpr int  CC = 8;
    constexpr int  NCH = CIN / CC;       // chunks: 10 / 16 / 8

    const float* xin = IS1 ? d_xin : (STAGE == 2 ? d_y1 : d_y2);
    float*       y   = IS1 ? d_y1  : (STAGE == 2 ? d_y2 : d_y3);
    const float* mean = (STAGE == 2) ? d_mean1 : d_mean2;
    const float* rstd = (STAGE == 2) ? d_rstd1 : d_rstd2;

    const int b  = blockIdx.z;
    const int t0 = blockIdx.x * BT;
    const int o0 = blockIdx.y * BO;
    const int tid = threadIdx.x;
    const int tx = tid & 15;    // t group (8 t's)
    const int ty = tid >> 4;    // o group (OT o's)

    __shared__ float  xs[2][CC][BT + 8];     // 8.5 KB
    __shared__ float2 wsd[2][CC][BO * 3];    // 24 KB (duplicated lanes)
    __shared__ float  sb[BO];
    __shared__ float  gA[CIN], gB[CIN];
    __shared__ float  sg[3 * BO];
    __shared__ int    sam[BT + 2];

    if constexpr (!IS1) {
        constexpr int CPG = CIN / 32;
        for (int c = tid; c < CIN; c += 256) {
            const int g = c / CPG;
            const float a = rstd[b * 32 + g] * gns[c];
            gA[c] = a;
            gB[c] = gnb[c] - mean[b * 32 + g] * a;
        }
    }
    if (tid < BO) sb[tid] = bias[o0 + tid];
    if constexpr (IS1) {
        for (int i = tid; i < 3 * BO; i += 256) {
            const int k = i / BO, o = i - k * BO;
            sg[i] = d_gdot[b * 3 * C1 + k * C1 + o0 + o];
        }
        for (int p = tid; p < BT + 2; p += 256) {
            const int t = t0 - 1 + p;
            sam[p] = (t >= 0 && t < T_) ? d_amax[b * T_ + t] : 0;
        }
    }
    __syncthreads();

    // stage chunk `ch` into buffer `buf`
    auto stage = [&](int ch, int buf) {
        const int c0 = ch * CC;
        for (int i = tid; i < CC * (BT + 2); i += 256) {
            const int cc = i / (BT + 2), p = i - cc * (BT + 2);
            const int t = t0 - 1 + p;
            const int c = c0 + cc;
            float v = 0.f;
            if (t >= 0 && t < T_) {
                v = xin[(b * CIN + c) * T_ + t];
                if constexpr (!IS1) v = fmaxf(fmaf(v, gA[c], gB[c]), 0.f);
            }
            xs[buf][cc][p] = v;
        }
        for (int i = tid; i < CC * BO * 3; i += 256) {
            const int cc = i / (BO * 3), r = i - cc * (BO * 3);
            const float v = w[(o0 + r / 3) * (CINW * 3) + (c0 + cc) * 3 + (r % 3)];
            wsd[buf][cc][r] = make_float2(v, v);
        }
    };

    u64 acc2[OT][4];
#pragma unroll
    for (int j = 0; j < OT; j++)
#pragma unroll
        for (int i = 0; i < 4; i++) acc2[j][i] = 0ull;

    stage(0, 0);
    __syncthreads();

    for (int ch = 0; ch < NCH; ch++) {
        const int buf = ch & 1;
        if (ch + 1 < NCH) stage(ch + 1, buf ^ 1);   // overlap with compute

#pragma unroll
        for (int cc = 0; cc < CC; cc++) {
            const float4* xp = reinterpret_cast<const float4*>(&xs[buf][cc][tx * 8]);
            const float4 a0 = xp[0], a1 = xp[1], a2 = xp[2];
            u64 pe[5], po[4];
            pe[0] = pk2(a0.x, a0.y); pe[1] = pk2(a0.z, a0.w);
            pe[2] = pk2(a1.x, a1.y); pe[3] = pk2(a1.z, a1.w);
            pe[4] = pk2(a2.x, a2.y);
            po[0] = pk2(a0.y, a0.z); po[1] = pk2(a0.w, a1.x);
            po[2] = pk2(a1.y, a1.z); po[3] = pk2(a1.w, a2.x);

            const u64* wrow = reinterpret_cast<const u64*>(&wsd[buf][cc][0]);
#pragma unroll
            for (int j = 0; j < OT; j++) {
                const int ol = ty * OT + j;
                const u64 w0 = wrow[ol * 3 + 0];
                const u64 w1v = wrow[ol * 3 + 1];
                const u64 w2 = wrow[ol * 3 + 2];
#pragma unroll
                for (int i = 0; i < 4; i++) {
                    ffma2(acc2[j][i], w0, pe[i]);
                    ffma2(acc2[j][i], w1v, po[i]);
                    ffma2(acc2[j][i], w2, pe[i + 1]);
                }
            }
        }
        __syncthreads();   // one barrier per chunk
    }

    // ------------------------- epilogue ------------------------------------
    float ov[OT][8];
#pragma unroll
    for (int j = 0; j < OT; j++)
#pragma unroll
        for (int i = 0; i < 4; i++)
            upk2(ov[j][2 * i], ov[j][2 * i + 1], acc2[j][i]);

    if constexpr (IS1) {
        const float4* sd4 = reinterpret_cast<const float4*>(
            d_sdot + (size_t)b * NCLS * 3 * C1);
        const int oq = (o0 >> 2) + ty;
#pragma unroll
        for (int i = 0; i < 8; i++) {
            const int tl = tx * 8 + i;
            const int t = t0 + tl;
            float4 s1 = sd4[(size_t)(sam[tl + 1] * 3 + 1) * 32 + oq];
            ov[0][i] += s1.x + sg[BO + ty * 4 + 0];
            ov[1][i] += s1.y + sg[BO + ty * 4 + 1];
            ov[2][i] += s1.z + sg[BO + ty * 4 + 2];
            ov[3][i] += s1.w + sg[BO + ty * 4 + 3];
            if (t > 0) {
                float4 s0 = sd4[(size_t)(sam[tl] * 3 + 0) * 32 + oq];
                ov[0][i] += s0.x + sg[ty * 4 + 0];
                ov[1][i] += s0.y + sg[ty * 4 + 1];
                ov[2][i] += s0.z + sg[ty * 4 + 2];
                ov[3][i] += s0.w + sg[ty * 4 + 3];
            }
            if (t < T_ - 1) {
                float4 s2 = sd4[(size_t)(sam[tl + 2] * 3 + 2) * 32 + oq];
                ov[0][i] += s2.x + sg[2 * BO + ty * 4 + 0];
                ov[1][i] += s2.y + sg[2 * BO + ty * 4 + 1];
                ov[2][i] += s2.z + sg[2 * BO + ty * 4 + 2];
                ov[3][i] += s2.w + sg[2 * BO + ty * 4 + 3];
            }
        }
    }

#pragma unroll
    for (int j = 0; j < OT; j++) {
        const int ol = ty * OT + j;
        const float bo = sb[ol];
        float4* yp = reinterpret_cast<float4*>(
            y + (size_t)(b * COUT + o0 + ol) * T_ + t0 + tx * 8);
        yp[0] = make_float4(ov[j][0] + bo, ov[j][1] + bo, ov[j][2] + bo, ov[j][3] + bo);
        yp[1] = make_float4(ov[j][4] + bo, ov[j][5] + bo, ov[j][6] + bo, ov[j][7] + bo);
    }
}

// ------------------------- GN stats ----------------------------------------
template <int STAGE>
__global__ void __launch_bounds__(256) k_gnstats() {
    constexpr int C   = (STAGE == 1) ? C1 : (STAGE == 2) ? C2 : C3;
    constexpr int CPG = C / 32;
    constexpr int N   = CPG * T_;
    const float* yv  = (STAGE == 1) ? d_y1 : (STAGE == 2) ? d_y2 : d_y3;
    float* meanp = (STAGE == 1) ? d_mean1 : (STAGE == 2) ? d_mean2 : d_mean3;
    float* rstdp = (STAGE == 1) ? d_rstd1 : (STAGE == 2) ? d_rstd2 : d_rstd3;

    const int bg = blockIdx.x;
    const float4* p = reinterpret_cast<const float4*>(
        yv + (size_t)(bg / 32) * C * T_ + (size_t)(bg % 32) * CPG * T_);
    float s = 0.f, s2 = 0.f;
    for (int i = threadIdx.x; i < N / 4; i += 256) {
        const float4 v = p[i];
        s += v.x + v.y + v.z + v.w;
        s2 = fmaf(v.x, v.x, fmaf(v.y, v.y, fmaf(v.z, v.z, fmaf(v.w, v.w, s2))));
    }
    __shared__ float ss[8], ss2[8];
#pragma unroll
    for (int o = 16; o; o >>= 1) {
        s  += __shfl_down_sync(0xffffffffu, s,  o);
        s2 += __shfl_down_sync(0xffffffffu, s2, o);
    }
    if ((threadIdx.x & 31) == 0) { ss[threadIdx.x >> 5] = s; ss2[threadIdx.x >> 5] = s2; }
    __syncthreads();
    if (threadIdx.x == 0) {
        float S = 0.f, S2 = 0.f;
#pragma unroll
        for (int i = 0; i < 8; i++) { S += ss[i]; S2 += ss2[i]; }
        const float m = S / N;
        const float var = S2 / N - m * m;
        meanp[bg] = m;
        rstdp[bg] = rsqrtf(var + 1e-5f);
    }
}

// ------------------------- conv4 (k=1) + output affine ---------------------
__global__ void __launch_bounds__(256)
k_out(const float* __restrict__ w4, const float* __restrict__ b4,
      const float* __restrict__ s3, const float* __restrict__ bb3,
      const float* __restrict__ omean, const float* __restrict__ ostd,
      float* __restrict__ out) {
    const int b = blockIdx.y;
    const int t = blockIdx.x * 256 + threadIdx.x;
    __shared__ float A[32], Bc[32], W[32];
    if (threadIdx.x < 32) {
        const int c = threadIdx.x;
        const float a = d_rstd3[b * 32 + c] * s3[c];
        A[c] = a;
        Bc[c] = bb3[c] - d_mean3[b * 32 + c] * a;
        W[c] = w4[c];
    }
    __syncthreads();
    float acc = b4[0];
#pragma unroll
    for (int c = 0; c < 32; c++) {
        float v = d_y3[(b * 32 + c) * T_ + t];
        v = fmaxf(fmaf(v, A[c], Bc[c]), 0.f);
        acc = fmaf(W[c], v, acc);
    }
    out[(size_t)t * NB + b] = fmaf(acc, ostd[0], omean[0]);
}

// ------------------------- launch ------------------------------------------
extern "C" void kernel_launch(void* const* d_in, const int* in_sizes, int n_in,
                              void* d_out, int out_size) {
    const float* input      = (const float*)d_in[0];
    const float* g_style    = (const float*)d_in[1];
    const float* char_style = (const float*)d_in[3];
    const float* c1w = (const float*)d_in[4];
    const float* c1b = (const float*)d_in[5];
    const float* g1s = (const float*)d_in[6];
    const float* g1b = (const float*)d_in[7];
    const float* c2w = (const float*)d_in[8];
    const float* c2b = (const float*)d_in[9];
    const float* g2s = (const float*)d_in[10];
    const float* g2b = (const float*)d_in[11];
    const float* c3w = (const float*)d_in[12];
    const float* c3b = (const float*)d_in[13];
    const float* g3s = (const float*)d_in[14];
    const float* g3b = (const float*)d_in[15];
    const float* c4w = (const float*)d_in[16];
    const float* c4b = (const float*)d_in[17];
    const float* om  = (const float*)d_in[18];
    const float* os  = (const float*)d_in[19];
    float* out = (float*)d_out;

    k_prep<<<dim3(T_ / 128, NB), 128>>>(input);
    k_gdot<<<NB, 384>>>(g_style, c1w);
    k_sdot<<<dim3(NCLS, NB), 384>>>(char_style, c1w);

    k_conv<1><<<dim3(T_ / 128, C1 / 64, NB), 256>>>(c1w, c1b, nullptr, nullptr);
    k_gnstats<1><<<NB * 32, 256>>>();

    k_conv<2><<<dim3(T_ / 128, 1, NB), 256>>>(c2w, c2b, g1s, g1b);
    k_gnstats<2><<<NB * 32, 256>>>();

    k_conv<3><<<dim3(T_ / 128, 1, NB), 256>>>(c3w, c3b, g2s, g2b);
    k_gnstats<3><<<NB * 32, 256>>>();

    k_out<<<dim3(T_ / 256, NB), 256>>>(c4w, c4b, g3s, g3b, om, os, out);
}